// round 4
// baseline (speedup 1.0000x reference)
#include <cuda_runtime.h>
#include <math.h>

// Problem dims
#define H   256
#define H2  512
#define H3  768
#define B   64
#define L   2048
#define V   32000
#define NCH 32              // l-chunks of 64
#define NB7 125             // k7 blocks (V/256)

typedef unsigned long long ull;

// ---------------- scratch (device globals) ----------------------------------------
__device__ __align__(16) float g_w2[H2];
__device__ __align__(16) float g_ehb[B];
__device__ __align__(16) float g_attn[B * L];       // energies -> weights in place
__device__ __align__(16) float g_pm[B * NCH];
__device__ __align__(16) float g_ps[B * NCH];
__device__ __align__(16) float g_ctxp[B * NCH * H]; // partial contexts
__device__ __align__(16) float g_xT[H2 * B];        // [emb; ctx] transposed [k][b]
__device__ __align__(16) float g_hT[H * B];         // hidden transposed [k][b]
__device__ __align__(16) float g_yT[H2 * B];        // [h_new; ctx] transposed [k][b]
__device__ __align__(16) float g_logits[B * V];
__device__ __align__(16) float g_lpm[B * 128];
__device__ __align__(16) float g_lps[B * 128];
__device__ __align__(16) float g_lse[B];
__device__ int g_cntA[B];
__device__ int g_cnt7;

__device__ __forceinline__ ull fma2(ull a, ull x, ull c) {
    asm("fma.rn.f32x2 %0, %1, %2, %3;" : "=l"(a) : "l"(x), "l"(c), "l"(a));
    return a;
}
__device__ __forceinline__ ull pack2(float w) {
    ull r;
    asm("mov.b64 %0, {%1, %1};" : "=l"(r) : "f"(w));
    return r;
}
__device__ __forceinline__ float lo32(ull a) { return __uint_as_float((unsigned)(a & 0xffffffffull)); }
__device__ __forceinline__ float hi32(ull a) { return __uint_as_float((unsigned)(a >> 32)); }

// ---------------- K1: w2, bias, e_h+bias, transposes, counter reset ---------------
__global__ void k1_prep(const float* __restrict__ attn_W,
                        const float* __restrict__ attn_b,
                        const float* __restrict__ flatten,
                        const float* __restrict__ hidden,
                        const int*   __restrict__ input,
                        const float* __restrict__ emb_table)
{
    __shared__ float s_f[H];
    __shared__ float s_wh[H];
    __shared__ float red[512];
    int tid = threadIdx.x;                      // 512 threads

    if (tid < 64) g_cntA[tid] = 0;
    if (tid == 64) g_cnt7 = 0;

    if (tid < H) s_f[tid] = flatten[tid];
    __syncthreads();

    // w2[j] = sum_i attn_W[i, j] * f[i]
    float acc = 0.f;
    #pragma unroll 8
    for (int i = 0; i < H; i++) acc += attn_W[i * H2 + tid] * s_f[i];
    g_w2[tid] = acc;
    if (tid < H) s_wh[tid] = acc;

    // bias = f . attn_b
    red[tid] = (tid < H) ? s_f[tid] * attn_b[tid] : 0.f;
    __syncthreads();
    for (int s = 256; s > 0; s >>= 1) {
        if (tid < s) red[tid] += red[tid + s];
        __syncthreads();
    }
    float bias = red[0];

    // e_h[b] = h[b] . w2[:H]
    int wid = tid >> 5, lane = tid & 31;
    #pragma unroll
    for (int i = 0; i < 4; i++) {
        int b = wid * 4 + i;
        float a = 0.f;
        #pragma unroll
        for (int c = 0; c < 8; c++) {
            int k = c * 32 + lane;
            a += hidden[b * H + k] * s_wh[k];
        }
        #pragma unroll
        for (int o = 16; o > 0; o >>= 1) a += __shfl_down_sync(0xffffffffu, a, o);
        if (lane == 0) g_ehb[b] = a + bias;
    }

    // transposes: emb -> xT[k<256], hidden -> hT
    for (int idx = tid; idx < B * H; idx += 512) {
        int b = idx >> 8, j = idx & 255;
        g_xT[j * B + b] = emb_table[(size_t)input[b] * H + j];
        g_hT[j * B + b] = hidden[idx];
    }
}

// ---------------- KA: fused energies + chunk softmax + partials + combine ---------
__global__ __launch_bounds__(256) void kA_attn(const float* __restrict__ enc,
                                               float* __restrict__ out_attn)
{
    extern __shared__ float sm[];
    float* tile = sm;                // 64*256
    float* s_w2 = sm + 64 * H;       // 256
    float* s_e  = s_w2 + H;          // 64
    float* s_w  = s_e + 64;          // 64
    float* s_m  = s_w + 64;          // 1
    int*   s_fl = (int*)(s_m + 1);   // combine flag

    int b = blockIdx.x >> 5;
    int c = blockIdx.x & 31;
    int tid = threadIdx.x;
    int l0 = c * 64;

    s_w2[tid] = g_w2[H + tid];

    const float4* src = (const float4*)(enc + ((size_t)l0 * B + b) * H);
    float4* t4 = (float4*)tile;
    #pragma unroll
    for (int i = 0; i < 16; i++) {
        int idx = tid + 256 * i;
        int row = idx >> 6, col = idx & 63;
        t4[row * 64 + col] = src[(size_t)row * 4096 + col];
    }
    __syncthreads();

    int wid = tid >> 5, lane = tid & 31;
    #pragma unroll
    for (int i = 0; i < 8; i++) {
        int l = wid * 8 + i;
        const float4* tr = (const float4*)(tile + l * H);
        const float4* w4 = (const float4*)s_w2;
        float4 t0 = tr[lane],      w0 = w4[lane];
        float4 t1 = tr[32 + lane], w1 = w4[32 + lane];
        float a = t0.x * w0.x + t0.y * w0.y + t0.z * w0.z + t0.w * w0.w
                + t1.x * w1.x + t1.y * w1.y + t1.z * w1.z + t1.w * w1.w;
        #pragma unroll
        for (int o = 16; o > 0; o >>= 1) a += __shfl_down_sync(0xffffffffu, a, o);
        if (lane == 0) {
            float e = a + g_ehb[b];
            s_e[l] = e;
            g_attn[b * L + l0 + l] = e;     // raw energy
        }
    }
    __syncthreads();

    if (wid == 0) {
        float m = fmaxf(s_e[lane], s_e[32 + lane]);
        #pragma unroll
        for (int o = 16; o > 0; o >>= 1) m = fmaxf(m, __shfl_xor_sync(0xffffffffu, m, o));
        if (lane == 0) s_m[0] = m;
    }
    __syncthreads();
    float m = s_m[0];
    if (tid < 64) s_w[tid] = __expf(s_e[tid] - m);
    __syncthreads();
    if (wid == 0) {
        float s = s_w[lane] + s_w[32 + lane];
        #pragma unroll
        for (int o = 16; o > 0; o >>= 1) s += __shfl_xor_sync(0xffffffffu, s, o);
        if (lane == 0) { g_pm[b * NCH + c] = m; g_ps[b * NCH + c] = s; }
    }
    __syncthreads();

    // partial context: thread = h
    float a0 = 0.f, a1 = 0.f, a2 = 0.f, a3 = 0.f;
    #pragma unroll
    for (int l = 0; l < 64; l += 4) {
        a0 += s_w[l + 0] * tile[(l + 0) * H + tid];
        a1 += s_w[l + 1] * tile[(l + 1) * H + tid];
        a2 += s_w[l + 2] * tile[(l + 2) * H + tid];
        a3 += s_w[l + 3] * tile[(l + 3) * H + tid];
    }
    g_ctxp[(size_t)(b * NCH + c) * H + tid] = (a0 + a1) + (a2 + a3);

    // last-block-done combine for this b
    __threadfence();
    __syncthreads();
    if (tid == 0) s_fl[0] = (atomicAdd(&g_cntA[b], 1) == NCH - 1) ? 1 : 0;
    __syncthreads();
    if (!s_fl[0]) return;

    // combine (reuse smem front as scale array)
    float* s_scale = sm;            // 32
    float* s_mi    = sm + 32;       // 2
    if (tid < 32) {
        float mc = g_pm[b * NCH + tid];
        float sc = g_ps[b * NCH + tid];
        float mm = mc;
        #pragma unroll
        for (int o = 16; o > 0; o >>= 1) mm = fmaxf(mm, __shfl_xor_sync(0xffffffffu, mm, o));
        float sca = __expf(mc - mm);
        float ss = sc * sca;
        #pragma unroll
        for (int o = 16; o > 0; o >>= 1) ss += __shfl_xor_sync(0xffffffffu, ss, o);
        s_scale[tid] = sca;
        if (tid == 0) { s_mi[0] = mm; s_mi[1] = 1.f / ss; }
    }
    __syncthreads();
    float mg = s_mi[0], inv = s_mi[1];

    // ctx[h] -> transposed into xT/yT second halves
    const float* cp = g_ctxp + (size_t)b * NCH * H + tid;
    float acc = 0.f;
    #pragma unroll 8
    for (int cc = 0; cc < NCH; cc++) acc += s_scale[cc] * cp[(size_t)cc * H];
    float ctxv = acc * inv;
    g_xT[(H + tid) * B + b] = ctxv;
    g_yT[(H + tid) * B + b] = ctxv;

    // attention weights
    for (int l = tid; l < L; l += 256) {
        float w = __expf(g_attn[b * L + l] - mg) * inv;
        g_attn[b * L + l] = w;
        if (out_attn) out_attn[b * L + l] = w;
    }
}

// ---------------- K56: fused GRU matvecs + gates, warp per hidden index j ---------
// b is the vector dim: 32 lanes x 2 b (f32x2). No reductions.
__global__ __launch_bounds__(256) void k56_gru(const float* __restrict__ Wih,
                                               const float* __restrict__ Whh,
                                               const float* __restrict__ bih,
                                               const float* __restrict__ bhh,
                                               float* __restrict__ out_h)
{
    extern __shared__ float sm[];
    float* s_x = sm;                 // [512][64] 128KB
    float* s_h = sm + H2 * B;        // [256][64] 64KB
    int tid = threadIdx.x;

    {
        const float4* sx = (const float4*)g_xT;
        float4* dx = (float4*)s_x;
        #pragma unroll
        for (int i = 0; i < (H2 * B / 4) / 256; i++) dx[tid + 256 * i] = sx[tid + 256 * i];
        const float4* sh = (const float4*)g_hT;
        float4* dh = (float4*)s_h;
        #pragma unroll
        for (int i = 0; i < (H * B / 4) / 256; i++) dh[tid + 256 * i] = sh[tid + 256 * i];
    }
    __syncthreads();

    int wid = tid >> 5, lane = tid & 31;
    int j = blockIdx.x * 8 + wid;               // 32 blocks * 8 warps = 256 j

    const float4* wr4 = (const float4*)(Wih + (size_t)j * H2);
    const float4* wz4 = (const float4*)(Wih + (size_t)(j + H) * H2);
    const float4* wn4 = (const float4*)(Wih + (size_t)(j + 2 * H) * H2);

    ull ar = 0, az = 0, an = 0;
    #pragma unroll 4
    for (int q = 0; q < H2 / 4; q++) {
        float4 vr = wr4[q], vz = wz4[q], vn = wn4[q];
        const float* w_r = (const float*)&vr;
        const float* w_z = (const float*)&vz;
        const float* w_n = (const float*)&vn;
        #pragma unroll
        for (int i = 0; i < 4; i++) {
            ull x2 = *(const ull*)(s_x + (q * 4 + i) * B + lane * 2);
            ar = fma2(ar, pack2(w_r[i]), x2);
            az = fma2(az, pack2(w_z[i]), x2);
            an = fma2(an, pack2(w_n[i]), x2);
        }
    }

    const float4* hr4 = (const float4*)(Whh + (size_t)j * H);
    const float4* hz4 = (const float4*)(Whh + (size_t)(j + H) * H);
    const float4* hn4 = (const float4*)(Whh + (size_t)(j + 2 * H) * H);
    ull br_ = 0, bz_ = 0, bn_ = 0;
    #pragma unroll 4
    for (int q = 0; q < H / 4; q++) {
        float4 vr = hr4[q], vz = hz4[q], vn = hn4[q];
        const float* w_r = (const float*)&vr;
        const float* w_z = (const float*)&vz;
        const float* w_n = (const float*)&vn;
        #pragma unroll
        for (int i = 0; i < 4; i++) {
            ull h2 = *(const ull*)(s_h + (q * 4 + i) * B + lane * 2);
            br_ = fma2(br_, pack2(w_r[i]), h2);
            bz_ = fma2(bz_, pack2(w_z[i]), h2);
            bn_ = fma2(bn_, pack2(w_n[i]), h2);
        }
    }

    float bir = bih[j], biz = bih[j + H], bin = bih[j + 2 * H];
    float bhr = bhh[j], bhz = bhh[j + H], bhn = bhh[j + 2 * H];
    float2 hp = *(const float2*)(s_h + j * B + lane * 2);

    float hn_out[2];
    #pragma unroll
    for (int d = 0; d < 2; d++) {
        float gir = (d ? hi32(ar) : lo32(ar)) + bir;
        float giz = (d ? hi32(az) : lo32(az)) + biz;
        float gin = (d ? hi32(an) : lo32(an)) + bin;
        float ghr = (d ? hi32(br_) : lo32(br_)) + bhr;
        float ghz = (d ? hi32(bz_) : lo32(bz_)) + bhz;
        float ghn = (d ? hi32(bn_) : lo32(bn_)) + bhn;
        float r = 1.f / (1.f + __expf(-(gir + ghr)));
        float z = 1.f / (1.f + __expf(-(giz + ghz)));
        float n = tanhf(gin + r * ghn);
        float hprev = d ? hp.y : hp.x;
        hn_out[d] = (1.f - z) * n + z * hprev;
    }
    *(float2*)(g_yT + j * B + lane * 2) = make_float2(hn_out[0], hn_out[1]);
    if (out_h) {
        out_h[(lane * 2 + 0) * H + j] = hn_out[0];
        out_h[(lane * 2 + 1) * H + j] = hn_out[1];
    }
}

// ---------------- K7: logits GEMM (smem-staged W, double-buffered) + lse ----------
#define KT 32               // k-chunk
#define WPITCH 33
#define SOUT_PITCH 257
__global__ __launch_bounds__(256) void k7_logits(const float* __restrict__ outW,
                                                 const float* __restrict__ outb)
{
    extern __shared__ float sm[];
    float* s_y = sm;                             // [512][64] 128KB
    float* s_w = sm + H2 * B;                    // 2 x [256][33] ~67.6KB
    int tid = threadIdx.x;

    {
        const float4* src = (const float4*)g_yT;
        float4* dst = (float4*)s_y;
        #pragma unroll
        for (int i = 0; i < (H2 * B / 4) / 256; i++) dst[tid + 256 * i] = src[tid + 256 * i];
    }

    int v0 = blockIdx.x * 256;
    int f4id = tid & 7;                          // k-quad within chunk
    int rbase = tid >> 3;                        // 0..31

    // prologue: load chunk 0
    float4 rw[8];
    #pragma unroll
    for (int rr = 0; rr < 8; rr++)
        rw[rr] = ((const float4*)outW)[(size_t)(v0 + rbase + 32 * rr) * 128 + f4id];
    #pragma unroll
    for (int rr = 0; rr < 8; rr++) {
        float* d = s_w + (rbase + 32 * rr) * WPITCH + f4id * 4;
        d[0] = rw[rr].x; d[1] = rw[rr].y; d[2] = rw[rr].z; d[3] = rw[rr].w;
    }
    __syncthreads();

    int tb = tid & 7;                            // 8 b-groups of 8
    int tv = tid >> 3;                           // 32 v-groups of 8
    int b0 = tb * 8;

    ull acc[8][4];
    #pragma unroll
    for (int j = 0; j < 8; j++)
        #pragma unroll
        for (int p = 0; p < 4; p++) acc[j][p] = 0ull;

    #pragma unroll 1
    for (int c = 0; c < H2 / KT; c++) {
        // prefetch next chunk into regs (overlaps compute)
        if (c + 1 < H2 / KT) {
            #pragma unroll
            for (int rr = 0; rr < 8; rr++)
                rw[rr] = ((const float4*)outW)[(size_t)(v0 + rbase + 32 * rr) * 128 + (c + 1) * 8 + f4id];
        }
        const float* wbuf = s_w + (c & 1) * (256 * WPITCH);
        #pragma unroll 4
        for (int kk = 0; kk < KT; kk++) {
            int k = c * KT + kk;
            ulonglong2 ya = *(const ulonglong2*)(s_y + k * B + b0);
            ulonglong2 yb = *(const ulonglong2*)(s_y + k * B + b0 + 4);
            ull y2[4] = { ya.x, ya.y, yb.x, yb.y };
            #pragma unroll
            for (int j = 0; j < 8; j++) {
                ull w2 = pack2(wbuf[(tv * 8 + j) * WPITCH + kk]);
                #pragma unroll
                for (int p = 0; p < 4; p++) acc[j][p] = fma2(acc[j][p], w2, y2[p]);
            }
        }
        if (c + 1 < H2 / KT) {
            float* wb2 = s_w + ((c + 1) & 1) * (256 * WPITCH);
            #pragma unroll
            for (int rr = 0; rr < 8; rr++) {
                float* d = wb2 + (rbase + 32 * rr) * WPITCH + f4id * 4;
                d[0] = rw[rr].x; d[1] = rw[rr].y; d[2] = rw[rr].z; d[3] = rw[rr].w;
            }
        }
        __syncthreads();
    }

    // epilogue: stage 64 x 256 tile, add bias
    float* s_out = s_y;                          // reuse (64*257 < 32768)
    float bb[8];
    #pragma unroll
    for (int j = 0; j < 8; j++) bb[j] = outb[v0 + tv * 8 + j];
    #pragma unroll
    for (int j = 0; j < 8; j++)
        #pragma unroll
        for (int p = 0; p < 4; p++) {
            int vl = tv * 8 + j;
            s_out[(b0 + 2 * p + 0) * SOUT_PITCH + vl] = lo32(acc[j][p]) + bb[j];
            s_out[(b0 + 2 * p + 1) * SOUT_PITCH + vl] = hi32(acc[j][p]) + bb[j];
        }
    __syncthreads();

    // coalesced copy to g_logits
    #pragma unroll
    for (int it = 0; it < (B * 256 / 4) / 256; it++) {
        int i = tid + it * 256;
        int v4 = i & 63, b = i >> 6;
        const float* s = s_out + b * SOUT_PITCH + v4 * 4;
        *(float4*)(g_logits + (size_t)b * V + v0 + v4 * 4) = make_float4(s[0], s[1], s[2], s[3]);
    }

    // lse partials over this 256-v tile (4 threads per b)
    {
        int bq = tid >> 2, i4 = tid & 3;
        const float* r = s_out + bq * SOUT_PITCH + i4 * 64;
        float m = -INFINITY;
        #pragma unroll
        for (int j = 0; j < 64; j++) m = fmaxf(m, r[j]);
        m = fmaxf(m, __shfl_xor_sync(0xffffffffu, m, 1));
        m = fmaxf(m, __shfl_xor_sync(0xffffffffu, m, 2));
        float s = 0.f;
        #pragma unroll
        for (int j = 0; j < 64; j++) s += __expf(r[j] - m);
        s += __shfl_xor_sync(0xffffffffu, s, 1);
        s += __shfl_xor_sync(0xffffffffu, s, 2);
        if (i4 == 0) {
            g_lpm[bq * 128 + blockIdx.x] = m;
            g_lps[bq * 128 + blockIdx.x] = s;
        }
    }

    // last block merges lse
    __shared__ int s_last;
    __threadfence();
    __syncthreads();
    if (tid == 0) s_last = (atomicAdd(&g_cnt7, 1) == NB7 - 1) ? 1 : 0;
    __syncthreads();
    if (!s_last) return;

    int bq = tid >> 2, i4 = tid & 3;
    float m = -INFINITY;
    for (int i = i4; i < NB7; i += 4) m = fmaxf(m, g_lpm[bq * 128 + i]);
    m = fmaxf(m, __shfl_xor_sync(0xffffffffu, m, 1));
    m = fmaxf(m, __shfl_xor_sync(0xffffffffu, m, 2));
    float s = 0.f;
    for (int i = i4; i < NB7; i += 4) s += g_lps[bq * 128 + i] * __expf(g_lpm[bq * 128 + i] - m);
    s += __shfl_xor_sync(0xffffffffu, s, 1);
    s += __shfl_xor_sync(0xffffffffu, s, 2);
    if (i4 == 0) g_lse[bq] = m + logf(s);
}

// ---------------- K8w: out = logits - lse[b] ---------------------------------------
__global__ void k8w_write(float* __restrict__ out)
{
    int idx = blockIdx.x * 256 + threadIdx.x;   // float4 index
    int b = idx / (V / 4);
    float lse = g_lse[b];
    float4 v = ((const float4*)g_logits)[idx];
    v.x -= lse; v.y -= lse; v.z -= lse; v.w -= lse;
    ((float4*)out)[idx] = v;
}

// ---------------- host launch ------------------------------------------------------
extern "C" void kernel_launch(void* const* d_in, const int* in_sizes, int n_in,
                              void* d_out, int out_size)
{
    int s = (n_in >= 14 && in_sizes[3] == 1) ? 0 : -1;
    const int*   input    = (const int*)  d_in[0];
    const float* hidden   = (const float*)d_in[1];
    const float* enc      = (const float*)d_in[2];
    const float* emb      = (const float*)d_in[4 + s];
    const float* attn_W   = (const float*)d_in[5 + s];
    const float* attn_b   = (const float*)d_in[6 + s];
    const float* flatten  = (const float*)d_in[7 + s];
    const float* Wih      = (const float*)d_in[8 + s];
    const float* Whh      = (const float*)d_in[9 + s];
    const float* bih      = (const float*)d_in[10 + s];
    const float* bhh      = (const float*)d_in[11 + s];
    const float* outW     = (const float*)d_in[12 + s];
    const float* outb     = (const float*)d_in[13 + s];

    float* dout     = (float*)d_out;
    float* out_h    = (out_size >= B * V + B * H) ? dout + B * V : nullptr;
    float* out_attn = (out_size >= B * V + B * H + B * L) ? dout + B * V + B * H : nullptr;

    k1_prep<<<1, 512>>>(attn_W, attn_b, flatten, hidden, input, emb);

    int smem_kA = (64 * H + H + 64 + 64 + 8) * (int)sizeof(float);
    cudaFuncSetAttribute(kA_attn, cudaFuncAttributeMaxDynamicSharedMemorySize, smem_kA);
    kA_attn<<<B * NCH, 256, smem_kA>>>(enc, out_attn);

    int smem_k56 = (H2 * B + H * B) * (int)sizeof(float);       // 192KB
    cudaFuncSetAttribute(k56_gru, cudaFuncAttributeMaxDynamicSharedMemorySize, smem_k56);
    k56_gru<<<32, 256, smem_k56>>>(Wih, Whh, bih, bhh, out_h);

    int smem_k7 = (H2 * B + 2 * 256 * WPITCH) * (int)sizeof(float);  // ~198.7KB
    cudaFuncSetAttribute(k7_logits, cudaFuncAttributeMaxDynamicSharedMemorySize, smem_k7);
    k7_logits<<<NB7, 256, smem_k7>>>(outW, outb);

    k8w_write<<<(B * V / 4) / 256, 256>>>(dout);
}